// round 15
// baseline (speedup 1.0000x reference)
#include <cuda_runtime.h>
#include <cuda_fp16.h>
#include <math.h>

#define GS   160
#define KD   128
#define NKS  16
#define FSCALE      262144.0f            // 2^18
#define INV_FSCALE  3.814697265625e-06f  // 2^-18

#define SPEC_GRID 608                    // persistent grid (GB300: 152 SMs)

__device__ __half2 g_tmp_h[3][KD][GS][GS];     // [t][kd][a_k][b]
__device__ __half2 g_field_h[3][GS][GS][KD];   // [t][h][w][kd]

// ---------------- packed f32x2 helpers (sm_103a) ----------------
typedef unsigned long long u64p;

__device__ __forceinline__ u64p pk2(float x, float y){
    u64p r; asm("mov.b64 %0, {%1, %2};" : "=l"(r) : "f"(x), "f"(y)); return r;
}
__device__ __forceinline__ void upk2(u64p p, float& x, float& y){
    asm("mov.b64 {%0, %1}, %2;" : "=f"(x), "=f"(y) : "l"(p));
}
__device__ __forceinline__ u64p fma2p(u64p a, u64p b, u64p c){
    u64p d; asm("fma.rn.f32x2 %0, %1, %2, %3;" : "=l"(d) : "l"(a), "l"(b), "l"(c)); return d;
}
__device__ __forceinline__ u64p mul2p(u64p a, u64p b){
    u64p d; asm("mul.rn.f32x2 %0, %1, %2;" : "=l"(d) : "l"(a), "l"(b)); return d;
}
__device__ __forceinline__ u64p add2p(u64p a, u64p b){
    u64p d; asm("add.rn.f32x2 %0, %1, %2;" : "=l"(d) : "l"(a), "l"(b)); return d;
}
__device__ __forceinline__ u64p neg2p(u64p a){    // flip both fp32 signs (1 LOP)
    return a ^ 0x8000000080000000ULL;
}
__device__ __forceinline__ u64p shfl2(u64p v, int m){
    return __shfl_xor_sync(0xffffffffu, v, m);
}

// Twiddles: stage constants + DFT-5 output twiddles, broadcast-packed.
struct Tw {
    u64p cc[5], ssp[5], gg[5];   // stage: (c,c), (s,s), (g,g)
    u64p tac[4], tas[4];         // ta r=1..4: (c,c), (s,s)
    int  k1;                     // brev5(lane)
};

__device__ __forceinline__ float softplus_scale(const float* __restrict__ alpha_params){
    float a0 = alpha_params[0];
    float bx = 10.0f * a0;
    float alpha = (bx > 1.0f) ? a0 : (log1pf(expf(fminf(bx, 1.0f))) * 0.1f);
    return alpha * (1.0f / 25600.0f) * FSCALE;
}

__device__ __forceinline__ void make_tw(Tw &tw, int lane){
#pragma unroll
    for (int s = 0; s < 5; s++){
        int H = 16 >> s;
        float cv = 1.0f, sv = 0.0f, g = 1.0f;
        if (lane & H){
            int j = lane & (H - 1);
            sincospif((float)j / (float)H, &sv, &cv);
            g = -1.0f;
        }
        tw.cc[s]  = pk2(cv, cv);
        tw.ssp[s] = pk2(sv, sv);
        tw.gg[s]  = pk2(g, g);
    }
    tw.k1 = (int)(__brev((unsigned)lane) >> 27);
#pragma unroll
    for (int r = 1; r < 5; r++){
        float sv, cv;
        sincospif((float)(lane * r) / 80.0f, &sv, &cv);
        tw.tac[r - 1] = pk2(cv, cv);
        tw.tas[r - 1] = pk2(sv, sv);
    }
}

// Inverse-sign DFT-160 across a warp, TWO rows batched in f32x2 lanes.
// re[j] = (rowA.re[L+32j], rowB.re[L+32j]); im[j] likewise.
// Out:   slot r holds X[r + 5*brev5(L)] of each row.
__device__ __forceinline__ void fft160x2(u64p re[5], u64p im[5], const Tw &tw){
    const float C1 =  0.30901699437494745f;
    const float C2 = -0.80901699437494734f;
    const float S1 =  0.95105651629515353f;
    const float S2 =  0.58778525229247314f;
    const u64p C1p  = pk2(C1, C1),  C2p = pk2(C2, C2);
    const u64p S1p  = pk2(S1, S1),  S2p = pk2(S2, S2);
    const u64p mS1p = pk2(-S1, -S1);
    const u64p NEG1 = pk2(-1.0f, -1.0f);

    // --- symmetric DFT-5, per component ---
    u64p s1r = add2p(re[1], re[4]),  d1r = fma2p(re[4], NEG1, re[1]);
    u64p s2r = add2p(re[2], re[3]),  d2r = fma2p(re[3], NEG1, re[2]);
    u64p s1i = add2p(im[1], im[4]),  d1i = fma2p(im[4], NEG1, im[1]);
    u64p s2i = add2p(im[2], im[3]),  d2i = fma2p(im[3], NEG1, im[2]);

    u64p o0r = add2p(re[0], add2p(s1r, s2r));
    u64p o0i = add2p(im[0], add2p(s1i, s2i));

    u64p uar = fma2p(s2r, C2p, fma2p(s1r, C1p, re[0]));
    u64p ubr = fma2p(s2r, C1p, fma2p(s1r, C2p, re[0]));
    u64p uai = fma2p(s2i, C2p, fma2p(s1i, C1p, im[0]));
    u64p ubi = fma2p(s2i, C1p, fma2p(s1i, C2p, im[0]));
    u64p war = fma2p(d2r, S2p,  mul2p(d1r, S1p));
    u64p wbr = fma2p(d2r, mS1p, mul2p(d1r, S2p));
    u64p wai = fma2p(d2i, S2p,  mul2p(d1i, S1p));
    u64p wbi = fma2p(d2i, mS1p, mul2p(d1i, S2p));

    // X1 = ua + i*wa ; X4 = ua - i*wa ; X2 = ub + i*wb ; X3 = ub - i*wb
    u64p X1r = fma2p(wai, NEG1, uar), X1i = add2p(uai, war);
    u64p X4r = add2p(uar, wai),       X4i = fma2p(war, NEG1, uai);
    u64p X2r = fma2p(wbi, NEG1, ubr), X2i = add2p(ubi, wbr);
    u64p X3r = add2p(ubr, wbi),       X3i = fma2p(wbr, NEG1, ubi);

    re[0] = o0r; im[0] = o0i;
    // twiddle ta[r]:  vr = Xr*c - Xi*s ; vi = Xi*c + Xr*s
    {
        u64p c = tw.tac[0], s = tw.tas[0], sn = neg2p(s);
        re[1] = fma2p(X1i, sn, mul2p(X1r, c));
        im[1] = fma2p(X1r, s,  mul2p(X1i, c));
    }
    {
        u64p c = tw.tac[1], s = tw.tas[1], sn = neg2p(s);
        re[2] = fma2p(X2i, sn, mul2p(X2r, c));
        im[2] = fma2p(X2r, s,  mul2p(X2i, c));
    }
    {
        u64p c = tw.tac[2], s = tw.tas[2], sn = neg2p(s);
        re[3] = fma2p(X3i, sn, mul2p(X3r, c));
        im[3] = fma2p(X3r, s,  mul2p(X3i, c));
    }
    {
        u64p c = tw.tac[3], s = tw.tas[3], sn = neg2p(s);
        re[4] = fma2p(X4i, sn, mul2p(X4r, c));
        im[4] = fma2p(X4r, s,  mul2p(X4i, c));
    }

    // --- DFT-32 across lanes (DIF radix-2, sign-folded) ---
#pragma unroll
    for (int s = 0; s < 5; s++){
        int H = 16 >> s;
        u64p c  = tw.cc[s];
        u64p sp = tw.ssp[s];
        u64p sn = neg2p(sp);
        u64p g  = tw.gg[s];
#pragma unroll
        for (int r = 0; r < 5; r++){
            u64p pre = shfl2(re[r], H);
            u64p pim = shfl2(im[r], H);
            u64p Tr = fma2p(re[r], g, pre);
            u64p Ti = fma2p(im[r], g, pim);
            re[r] = fma2p(Ti, sn, mul2p(Tr, c));
            im[r] = fma2p(Tr, sp, mul2p(Ti, c));
        }
    }
}

// Persistent pass 1: grid(SPEC_GRID) x 256. 1920 tiles (640 per tensor).
__global__ void __launch_bounds__(256)
pass1_kernel(const float* __restrict__ pur, const float* __restrict__ pui,
             const float* __restrict__ pvr, const float* __restrict__ pvi,
             const float* __restrict__ pwr, const float* __restrict__ pwi,
             const float* __restrict__ alpha_params)
{
    __shared__ char smbuf[48640];
    int wid  = threadIdx.x >> 5;
    int lane = threadIdx.x & 31;
    float scale = softplus_scale(alpha_params);

    Tw tw; make_tw(tw, lane);

#pragma unroll 1
    for (int tile = blockIdx.x; tile < 1920; tile += SPEC_GRID){
        int z  = tile / 640;
        int id = tile - z * 640;

        if (z < 2){
            // ---- t01 tile: one kd, 32 rows; each warp 2 row-pairs ----
            int kd = id / 5;
            int bx = id - kd * 5;
            const float* rep = (z == 0) ? pur : pvr;
            const float* imp = (z == 0) ? pui : pvi;
            int k = kd >> 3, d = kd & 7;

            __half2* sm1 = (__half2*)smbuf;   // [a_k]*33 + rowlocal(0..31)

#pragma unroll 1
            for (int rp = 0; rp < 2; rp++){
                int rlA = wid * 4 + rp * 2;
                int bA  = bx * 32 + rlA;
                int baseA = (z == 0) ? ((kd * GS + bA) * GS)
                                     : (((k * GS + bA) * 8 + d) * GS);
                int baseB = (z == 0) ? ((kd * GS + bA + 1) * GS)
                                     : (((k * GS + bA + 1) * 8 + d) * GS);
                u64p re[5], im[5];
#pragma unroll
                for (int j = 0; j < 5; j++){
                    int off = lane + 32 * j;
                    re[j] = pk2(rep[baseA + off] * scale, rep[baseB + off] * scale);
                    im[j] = pk2(imp[baseA + off] * scale, imp[baseB + off] * scale);
                }
                fft160x2(re, im, tw);
#pragma unroll
                for (int r2 = 0; r2 < 5; r2++){
                    float ar, br, ai, bi;
                    upk2(re[r2], ar, br);
                    upk2(im[r2], ai, bi);
                    int row = (r2 + 5 * tw.k1) * 33;
                    sm1[row + rlA]     = __floats2half2_rn(ar, ai);
                    sm1[row + rlA + 1] = __floats2half2_rn(br, bi);
                }
            }
            __syncthreads();

#pragma unroll 1
            for (int idx = threadIdx.x; idx < GS * 8; idx += 256){
                int w = idx >> 3, g = idx & 7;
                const __half2* p = &sm1[w * 33 + g * 4];
                uint4 val;
                val.x = *(const unsigned*)&p[0];
                val.y = *(const unsigned*)&p[1];
                val.z = *(const unsigned*)&p[2];
                val.w = *(const unsigned*)&p[3];
                *(uint4*)&g_tmp_h[z][kd][w][bx * 32 + g * 4] = val;
            }
        } else {
            // ---- Pw tile: one k, 4 Y rows (2 pairs), all 8 d ----
            int k  = id / 40;
            int yb = id - k * 40;

            unsigned* smw  = (unsigned*)smbuf;                 // [y][X*9 + d] (pad 9)
            __half2*  sm1w = (__half2*)(smbuf + 4 * 1440 * 4); // [d][x_k*5 + y]

            {
                const float4* re4 = (const float4*)pwr;
                const float4* im4 = (const float4*)pwi;
                int y0 = yb * 4;
#pragma unroll 1
                for (int i = threadIdx.x; i < 1280; i += 256){
                    int X   = i >> 3;
                    int rem = i & 7;
                    int y   = rem >> 1;
                    int dg  = (rem & 1) * 4;
                    int gidx = ((k * GS + X) * GS + y0 + y) * 2 + (rem & 1);
                    float4 fr = re4[gidx];
                    float4 fi = im4[gidx];
                    unsigned* dst = &smw[y * 1440 + X * 9 + dg];
                    __half2 h0 = __floats2half2_rn(fr.x * scale, fi.x * scale);
                    __half2 h1 = __floats2half2_rn(fr.y * scale, fi.y * scale);
                    __half2 h2 = __floats2half2_rn(fr.z * scale, fi.z * scale);
                    __half2 h3 = __floats2half2_rn(fr.w * scale, fi.w * scale);
                    dst[0] = *(unsigned*)&h0;
                    dst[1] = *(unsigned*)&h1;
                    dst[2] = *(unsigned*)&h2;
                    dst[3] = *(unsigned*)&h3;
                }
            }
            __syncthreads();

#pragma unroll 1
            for (int yp = 0; yp < 2; yp++){
                u64p re[5], im[5];
#pragma unroll
                for (int j = 0; j < 5; j++){
                    unsigned uA = smw[(yp * 2)     * 1440 + (lane + 32 * j) * 9 + wid];
                    unsigned uB = smw[(yp * 2 + 1) * 1440 + (lane + 32 * j) * 9 + wid];
                    float2 fA = __half22float2(*(__half2*)&uA);
                    float2 fB = __half22float2(*(__half2*)&uB);
                    re[j] = pk2(fA.x, fB.x);
                    im[j] = pk2(fA.y, fB.y);
                }
                fft160x2(re, im, tw);
#pragma unroll
                for (int r2 = 0; r2 < 5; r2++){
                    float ar, br, ai, bi;
                    upk2(re[r2], ar, br);
                    upk2(im[r2], ai, bi);
                    int rowo = wid * 800 + (r2 + 5 * tw.k1) * 5;
                    sm1w[rowo + yp * 2]     = __floats2half2_rn(ar, ai);
                    sm1w[rowo + yp * 2 + 1] = __floats2half2_rn(br, bi);
                }
            }
            __syncthreads();

#pragma unroll 1
            for (int i = threadIdx.x; i < 1280; i += 256){
                int d = i / 160;
                int x = i - d * 160;
                const __half2* p = &sm1w[d * 800 + x * 5];
                uint4 val;
                val.x = *(const unsigned*)&p[0];
                val.y = *(const unsigned*)&p[1];
                val.z = *(const unsigned*)&p[2];
                val.w = *(const unsigned*)&p[3];
                *(uint4*)&g_tmp_h[2][k * 8 + d][x][yb * 4] = val;
            }
        }
        __syncthreads();   // smbuf reuse barrier before next tile
    }
}

// Persistent pass 2: grid(SPEC_GRID) x 256. 960 tiles; 4 row-pairs per warp.
__global__ void __launch_bounds__(256)
pass2_kernel()
{
    int wid  = threadIdx.x >> 5;
    int lane = threadIdx.x & 31;

    Tw tw; make_tw(tw, lane);

    __shared__ __half2 sm2[GS * 65];   // [h_k]*65 + ww*8 + wid

#pragma unroll 1
    for (int tile = blockIdx.x; tile < 960; tile += SPEC_GRID){
        int t  = tile / 320;
        int rr = tile - t * 320;
        int kb = rr / 20;
        int wb = rr - kb * 20;
        int kd = kb * 8 + wid;

#pragma unroll 1
        for (int wp = 0; wp < 4; wp++){
            const __half2* srcA = &g_tmp_h[t][kd][wb * 8 + wp * 2][0];
            const __half2* srcB = srcA + GS;
            u64p re[5], im[5];
#pragma unroll
            for (int j = 0; j < 5; j++){
                float2 fA = __half22float2(srcA[lane + 32 * j]);
                float2 fB = __half22float2(srcB[lane + 32 * j]);
                re[j] = pk2(fA.x, fB.x);
                im[j] = pk2(fA.y, fB.y);
            }
            fft160x2(re, im, tw);
#pragma unroll
            for (int r2 = 0; r2 < 5; r2++){
                float ar, br, ai, bi;
                upk2(re[r2], ar, br);
                upk2(im[r2], ai, bi);
                int rowo = (r2 + 5 * tw.k1) * 65;
                sm2[rowo + (wp * 2)     * 8 + wid] = __floats2half2_rn(ar, ai);
                sm2[rowo + (wp * 2 + 1) * 8 + wid] = __floats2half2_rn(br, bi);
            }
        }
        __syncthreads();

#pragma unroll 1
        for (int idx = threadIdx.x; idx < GS * 16; idx += 256){
            int h = idx >> 4, rem = idx & 15, ww = rem >> 1, q = rem & 1;
            const __half2* p = &sm2[h * 65 + ww * 8 + q * 4];
            uint4 val;
            val.x = *(const unsigned*)&p[0];
            val.y = *(const unsigned*)&p[1];
            val.z = *(const unsigned*)&p[2];
            val.w = *(const unsigned*)&p[3];
            *(uint4*)&g_field_h[t][h][wb * 8 + ww][kb * 8 + q * 4] = val;
        }
        __syncthreads();
    }
}

// Sample: 8 lanes per point (4 points/warp), dense cell loads.
__global__ void __launch_bounds__(256)
sample_kernel(const float* __restrict__ xyz,
              const float* __restrict__ boundp,
              float* __restrict__ out, int npts)
{
    int warp_g = (int)((blockIdx.x * (unsigned)blockDim.x + threadIdx.x) >> 5);
    int lane = threadIdx.x & 31;
    int sub  = lane >> 3;
    int sl2  = lane & 7;
    int gw   = warp_g * 4 + sub;
    if (gw >= npts) return;

    float invb = 1.0f / boundp[0];
    float p[3];
    p[0] = xyz[3*gw + 0] * invb;
    p[1] = xyz[3*gw + 1] * invb;
    p[2] = xyz[3*gw + 2] * invb;

    float wa0[3], wa1[3];
    int   c0i[3], c1i[3];
#pragma unroll
    for (int a = 0; a < 3; a++){
        float ia = (p[a] + 1.0f) * 0.5f * 159.0f;
        float fl = floorf(ia);
        float w  = ia - fl;
        int i0 = (int)fl, i1 = i0 + 1;
        float v0 = (i0 >= 0 && i0 <= 159) ? 1.0f : 0.0f;
        float v1 = (i1 >= 0 && i1 <= 159) ? 1.0f : 0.0f;
        c0i[a] = max(0, min(159, i0));
        c1i[a] = max(0, min(159, i1));
        wa0[a] = (1.0f - w) * v0;
        wa1[a] = w * v1;
    }

    const __half2* fld = &g_field_h[0][0][0][0];
    bool hi = (sl2 & 1) != 0;
    float acc0 = 0.0f, acc1 = 0.0f, acc2 = 0.0f, acc3 = 0.0f;

#pragma unroll
    for (int t = 0; t < 3; t++){
        const int ax = (t == 2) ? 0 : 2;
        const int ay = (t == 1) ? 0 : 1;

        __half2 w00h = __float2half2_rn(wa0[ax] * wa0[ay]);
        __half2 w01h = __float2half2_rn(wa1[ax] * wa0[ay]);
        __half2 w10h = __float2half2_rn(wa0[ax] * wa1[ay]);
        __half2 w11h = __float2half2_rn(wa1[ax] * wa1[ay]);

        int i0 = c0i[ax], i1 = c1i[ax];
        int j0 = c0i[ay], j1 = c1i[ay];

        const __half2* bp = fld + t * GS * GS * KD;
        const uint4* q00 = (const uint4*)(bp + (j0 * GS + i0) * KD) + sl2;
        const uint4* q01 = (const uint4*)(bp + (j0 * GS + i1) * KD) + sl2;
        const uint4* q10 = (const uint4*)(bp + (j1 * GS + i0) * KD) + sl2;
        const uint4* q11 = (const uint4*)(bp + (j1 * GS + i1) * KD) + sl2;

        float xt = (p[t] + 1.0f) * 0.5f;
        float s1, c1;
        sincospif(2.0f * xt, &s1, &c1);
        float cd[8], sd[8];
        cd[0] = 1.0f; sd[0] = 0.0f;
        float cc = c1, ss = s1;
        cd[1] = 2.0f * cc; sd[1] = 2.0f * ss;
#pragma unroll
        for (int j = 2; j < 8; j++){
            float nc = cc * cc - ss * ss;
            float ns = 2.0f * cc * ss;
            cc = nc; ss = ns;
            cd[j] = 2.0f * cc; sd[j] = 2.0f * ss;
        }
        float cs0 = hi ? cd[4] : cd[0], ss0 = hi ? sd[4] : sd[0];
        float cs1 = hi ? cd[5] : cd[1], ss1 = hi ? sd[5] : sd[1];
        float cs2 = hi ? cd[6] : cd[2], ss2 = hi ? sd[6] : sd[2];
        float cs3 = hi ? cd[7] : cd[3], ss3 = hi ? sd[7] : sd[3];

#pragma unroll 2
        for (int g = 0; g < 4; g++){
            uint4 u00 = q00[g * 8], u01 = q01[g * 8];
            uint4 u10 = q10[g * 8], u11 = q11[g * 8];
            float acc_s = 0.0f;
#pragma unroll
            for (int c = 0; c < 4; c++){
                __half2 acc = __hmul2(*(__half2*)&((&u00.x)[c]), w00h);
                acc = __hfma2(*(__half2*)&((&u01.x)[c]), w01h, acc);
                acc = __hfma2(*(__half2*)&((&u10.x)[c]), w10h, acc);
                acc = __hfma2(*(__half2*)&((&u11.x)[c]), w11h, acc);
                float2 f = __half22float2(acc);
                float csv = (c == 0) ? cs0 : (c == 1) ? cs1 : (c == 2) ? cs2 : cs3;
                float ssv = (c == 0) ? ss0 : (c == 1) ? ss1 : (c == 2) ? ss2 : ss3;
                acc_s += f.x * csv - f.y * ssv;
            }
            if      (g == 0) acc0 += acc_s;
            else if (g == 1) acc1 += acc_s;
            else if (g == 2) acc2 += acc_s;
            else             acc3 += acc_s;
        }
    }

    acc0 += __shfl_xor_sync(0xffffffffu, acc0, 1);
    acc1 += __shfl_xor_sync(0xffffffffu, acc1, 1);
    acc2 += __shfl_xor_sync(0xffffffffu, acc2, 1);
    acc3 += __shfl_xor_sync(0xffffffffu, acc3, 1);

    int q = sl2 >> 1;
    float* po = out + gw * NKS;
    if (!hi){
        po[q]      = acc0 * INV_FSCALE;
        po[4 + q]  = acc1 * INV_FSCALE;
    } else {
        po[8 + q]  = acc2 * INV_FSCALE;
        po[12 + q] = acc3 * INV_FSCALE;
    }
}

extern "C" void kernel_launch(void* const* d_in, const int* in_sizes, int n_in,
                              void* d_out, int out_size)
{
    const float* xyz   = (const float*)d_in[0];
    const float* bound = (const float*)d_in[1];
    const float* alpha = (const float*)d_in[2];
    const float* pur   = (const float*)d_in[3];
    const float* pui   = (const float*)d_in[4];
    const float* pvr   = (const float*)d_in[5];
    const float* pvi   = (const float*)d_in[6];
    const float* pwr   = (const float*)d_in[7];
    const float* pwi   = (const float*)d_in[8];

    pass1_kernel<<<SPEC_GRID, 256>>>(pur, pui, pvr, pvi, pwr, pwi, alpha);
    pass2_kernel<<<SPEC_GRID, 256>>>();

    int npts = in_sizes[0] / 3;
    int nwarps = (npts + 3) / 4;
    int nblocks = (nwarps * 32 + 255) / 256;
    sample_kernel<<<nblocks, 256>>>(xyz, bound, (float*)d_out, npts);
}

// round 16
// speedup vs baseline: 1.0572x; 1.0572x over previous
#include <cuda_runtime.h>
#include <cuda_fp16.h>
#include <math.h>

#define GS   160
#define KD   128
#define NKS  16
#define FSCALE      262144.0f            // 2^18
#define INV_FSCALE  3.814697265625e-06f  // 2^-18

#define SPEC_GRID 608                    // persistent grid (GB300: 152 SMs)

__device__ __half2 g_tmp_h[3][KD][GS][GS];     // [t][kd][a_k][b]
__device__ __half2 g_field_h[3][GS][GS][KD];   // [t][h][w][kd]

// ---------------- packed f32x2 helpers (sm_103a) ----------------
typedef unsigned long long u64p;

__device__ __forceinline__ u64p pk2(float x, float y){
    u64p r; asm("mov.b64 %0, {%1, %2};" : "=l"(r) : "f"(x), "f"(y)); return r;
}
__device__ __forceinline__ void upk2(u64p p, float& x, float& y){
    asm("mov.b64 {%0, %1}, %2;" : "=f"(x), "=f"(y) : "l"(p));
}
__device__ __forceinline__ u64p swp2(u64p p){
    float x, y; upk2(p, x, y); return pk2(y, x);
}
__device__ __forceinline__ u64p fma2p(u64p a, u64p b, u64p c){
    u64p d; asm("fma.rn.f32x2 %0, %1, %2, %3;" : "=l"(d) : "l"(a), "l"(b), "l"(c)); return d;
}
__device__ __forceinline__ u64p mul2p(u64p a, u64p b){
    u64p d; asm("mul.rn.f32x2 %0, %1, %2;" : "=l"(d) : "l"(a), "l"(b)); return d;
}
__device__ __forceinline__ u64p add2p(u64p a, u64p b){
    u64p d; asm("add.rn.f32x2 %0, %1, %2;" : "=l"(d) : "l"(a), "l"(b)); return d;
}
__device__ __forceinline__ u64p cmulp(u64p T, u64p tc, u64p ts){
    return fma2p(swp2(T), ts, mul2p(T, tc));
}

struct Tw {
    u64p stc[5], sts[5], g2[5];
    u64p tac[4], tas[4];
    int  k1;
};

__device__ __forceinline__ float softplus_scale(const float* __restrict__ alpha_params){
    float a0 = alpha_params[0];
    float bx = 10.0f * a0;
    float alpha = (bx > 1.0f) ? a0 : (log1pf(expf(fminf(bx, 1.0f))) * 0.1f);
    return alpha * (1.0f / 25600.0f) * FSCALE;
}

__device__ __forceinline__ void make_tw(Tw &tw, int lane){
#pragma unroll
    for (int s = 0; s < 5; s++){
        int H = 16 >> s;
        float cv = 1.0f, sv = 0.0f, g = 1.0f;
        if (lane & H){
            int j = lane & (H - 1);
            sincospif((float)j / (float)H, &sv, &cv);
            g = -1.0f;
        }
        tw.stc[s] = pk2(cv, cv);
        tw.sts[s] = pk2(-sv, sv);
        tw.g2[s]  = pk2(g, g);
    }
    tw.k1 = (int)(__brev((unsigned)lane) >> 27);
#pragma unroll
    for (int r = 1; r < 5; r++){
        float sv, cv;
        sincospif((float)(lane * r) / 80.0f, &sv, &cv);
        tw.tac[r - 1] = pk2(cv, cv);
        tw.tas[r - 1] = pk2(-sv, sv);
    }
}

// Inverse-sign DFT-160 across a warp, stride-1 input mapping, packed f32x2.
__device__ __forceinline__ void fft160p(u64p v[5], u64p o[5], const Tw &tw, int lane){
    const float C1 =  0.30901699437494745f;
    const float C2 = -0.80901699437494734f;
    const float S1 =  0.95105651629515353f;
    const float S2 =  0.58778525229247314f;
    const u64p C1p  = pk2(C1, C1),  C2p = pk2(C2, C2);
    const u64p S1p  = pk2(S1, S1),  S2p = pk2(S2, S2);
    const u64p mS1p = pk2(-S1, -S1);
    const u64p NEG1 = pk2(-1.0f, -1.0f);
    const u64p PM   = pk2(-1.0f, 1.0f);
    const u64p MP   = pk2(1.0f, -1.0f);

    u64p s1 = add2p(v[1], v[4]);
    u64p d1 = fma2p(v[4], NEG1, v[1]);
    u64p s2 = add2p(v[2], v[3]);
    u64p d2 = fma2p(v[3], NEG1, v[2]);
    o[0] = add2p(v[0], add2p(s1, s2));
    u64p ua = fma2p(s2, C2p, fma2p(s1, C1p, v[0]));
    u64p ub = fma2p(s2, C1p, fma2p(s1, C2p, v[0]));
    u64p wa = fma2p(d2, S2p,  mul2p(d1, S1p));
    u64p wb = fma2p(d2, mS1p, mul2p(d1, S2p));
    u64p X1 = fma2p(swp2(wa), PM, ua);
    u64p X4 = fma2p(swp2(wa), MP, ua);
    u64p X2 = fma2p(swp2(wb), PM, ub);
    u64p X3 = fma2p(swp2(wb), MP, ub);
    o[1] = cmulp(X1, tw.tac[0], tw.tas[0]);
    o[2] = cmulp(X2, tw.tac[1], tw.tas[1]);
    o[3] = cmulp(X3, tw.tac[2], tw.tas[2]);
    o[4] = cmulp(X4, tw.tac[3], tw.tas[3]);

#pragma unroll
    for (int s = 0; s < 5; s++){
        int H = 16 >> s;
#pragma unroll
        for (int r = 0; r < 5; r++){
            float ox, oy; upk2(o[r], ox, oy);
            float px = __shfl_xor_sync(0xffffffffu, ox, H);
            float py = __shfl_xor_sync(0xffffffffu, oy, H);
            u64p T = fma2p(o[r], tw.g2[s], pk2(px, py));
            o[r] = cmulp(T, tw.stc[s], tw.sts[s]);
        }
    }
}

// Persistent pass 1: grid(SPEC_GRID) x 256. 1920 tiles (640 per tensor).
__global__ void __launch_bounds__(256)
pass1_kernel(const float* __restrict__ pur, const float* __restrict__ pui,
             const float* __restrict__ pvr, const float* __restrict__ pvi,
             const float* __restrict__ pwr, const float* __restrict__ pwi,
             const float* __restrict__ alpha_params)
{
    __shared__ char smbuf[48640];
    int wid  = threadIdx.x >> 5;
    int lane = threadIdx.x & 31;
    float scale = softplus_scale(alpha_params);

    Tw tw; make_tw(tw, lane);

#pragma unroll 1
    for (int tile = blockIdx.x; tile < 1920; tile += SPEC_GRID){
        int z  = tile / 640;
        int id = tile - z * 640;

        if (z < 2){
            int kd = id / 5;
            int bx = id - kd * 5;
            const float* re = (z == 0) ? pur : pvr;
            const float* im = (z == 0) ? pui : pvi;
            int k = kd >> 3, d = kd & 7;

            __half2* sm1 = (__half2*)smbuf;

#pragma unroll 1
            for (int r = 0; r < 4; r++){
                int rl = wid * 4 + r;
                int b  = bx * 32 + rl;
                int base = (z == 0) ? ((kd * GS + b) * GS)
                                    : (((k * GS + b) * 8 + d) * GS);
                u64p v[5], o[5];
#pragma unroll
                for (int j = 0; j < 5; j++){
                    int idx = base + lane + 32 * j;
                    v[j] = pk2(re[idx] * scale, im[idx] * scale);
                }
                fft160p(v, o, tw, lane);
#pragma unroll
                for (int r2 = 0; r2 < 5; r2++){
                    float x, y; upk2(o[r2], x, y);
                    sm1[(r2 + 5 * tw.k1) * 33 + rl] = __floats2half2_rn(x, y);
                }
            }
            __syncthreads();

#pragma unroll 1
            for (int idx = threadIdx.x; idx < GS * 8; idx += 256){
                int w = idx >> 3, g = idx & 7;
                const __half2* p = &sm1[w * 33 + g * 4];
                uint4 val;
                val.x = *(const unsigned*)&p[0];
                val.y = *(const unsigned*)&p[1];
                val.z = *(const unsigned*)&p[2];
                val.w = *(const unsigned*)&p[3];
                *(uint4*)&g_tmp_h[z][kd][w][bx * 32 + g * 4] = val;
            }
        } else {
            int k  = id / 40;
            int yb = id - k * 40;

            unsigned* smw  = (unsigned*)smbuf;
            __half2*  sm1w = (__half2*)(smbuf + 4 * 1440 * 4);

            {
                const float4* re4 = (const float4*)pwr;
                const float4* im4 = (const float4*)pwi;
                int y0 = yb * 4;
#pragma unroll 1
                for (int i = threadIdx.x; i < 1280; i += 256){
                    int X   = i >> 3;
                    int rem = i & 7;
                    int y   = rem >> 1;
                    int dg  = (rem & 1) * 4;
                    int gidx = ((k * GS + X) * GS + y0 + y) * 2 + (rem & 1);
                    float4 fr = re4[gidx];
                    float4 fi = im4[gidx];
                    unsigned* dst = &smw[y * 1440 + X * 9 + dg];
                    __half2 h0 = __floats2half2_rn(fr.x * scale, fi.x * scale);
                    __half2 h1 = __floats2half2_rn(fr.y * scale, fi.y * scale);
                    __half2 h2 = __floats2half2_rn(fr.z * scale, fi.z * scale);
                    __half2 h3 = __floats2half2_rn(fr.w * scale, fi.w * scale);
                    dst[0] = *(unsigned*)&h0;
                    dst[1] = *(unsigned*)&h1;
                    dst[2] = *(unsigned*)&h2;
                    dst[3] = *(unsigned*)&h3;
                }
            }
            __syncthreads();

#pragma unroll 1
            for (int yr = 0; yr < 4; yr++){
                u64p v[5], o[5];
#pragma unroll
                for (int j = 0; j < 5; j++){
                    unsigned u = smw[yr * 1440 + (lane + 32 * j) * 9 + wid];
                    float2 f = __half22float2(*(__half2*)&u);
                    v[j] = pk2(f.x, f.y);
                }
                fft160p(v, o, tw, lane);
#pragma unroll
                for (int r2 = 0; r2 < 5; r2++){
                    float x, y; upk2(o[r2], x, y);
                    sm1w[wid * 800 + (r2 + 5 * tw.k1) * 5 + yr] = __floats2half2_rn(x, y);
                }
            }
            __syncthreads();

#pragma unroll 1
            for (int i = threadIdx.x; i < 1280; i += 256){
                int d = i / 160;
                int x = i - d * 160;
                const __half2* p = &sm1w[d * 800 + x * 5];
                uint4 val;
                val.x = *(const unsigned*)&p[0];
                val.y = *(const unsigned*)&p[1];
                val.z = *(const unsigned*)&p[2];
                val.w = *(const unsigned*)&p[3];
                *(uint4*)&g_tmp_h[2][k * 8 + d][x][yb * 4] = val;
            }
        }
        __syncthreads();
    }
}

// Persistent pass 2: grid(SPEC_GRID) x 256. 960 tiles.
__global__ void __launch_bounds__(256)
pass2_kernel()
{
    int wid  = threadIdx.x >> 5;
    int lane = threadIdx.x & 31;

    Tw tw; make_tw(tw, lane);

    __shared__ __half2 sm2[GS * 65];

#pragma unroll 1
    for (int tile = blockIdx.x; tile < 960; tile += SPEC_GRID){
        int t  = tile / 320;
        int rr = tile - t * 320;
        int kb = rr / 20;
        int wb = rr - kb * 20;
        int kd = kb * 8 + wid;

#pragma unroll 1
        for (int ww = 0; ww < 8; ww++){
            const __half2* src = &g_tmp_h[t][kd][wb * 8 + ww][0];
            u64p v[5], o[5];
#pragma unroll
            for (int j = 0; j < 5; j++){
                float2 f = __half22float2(src[lane + 32 * j]);
                v[j] = pk2(f.x, f.y);
            }
            fft160p(v, o, tw, lane);
#pragma unroll
            for (int r2 = 0; r2 < 5; r2++){
                float x, y; upk2(o[r2], x, y);
                sm2[(r2 + 5 * tw.k1) * 65 + ww * 8 + wid] = __floats2half2_rn(x, y);
            }
        }
        __syncthreads();

#pragma unroll 1
        for (int idx = threadIdx.x; idx < GS * 16; idx += 256){
            int h = idx >> 4, rem = idx & 15, ww = rem >> 1, q = rem & 1;
            const __half2* p = &sm2[h * 65 + ww * 8 + q * 4];
            uint4 val;
            val.x = *(const unsigned*)&p[0];
            val.y = *(const unsigned*)&p[1];
            val.z = *(const unsigned*)&p[2];
            val.w = *(const unsigned*)&p[3];
            *(uint4*)&g_field_h[t][h][wb * 8 + ww][kb * 8 + q * 4] = val;
        }
        __syncthreads();
    }
}

// Sample: 8 lanes per point (4 points/warp), dense cell loads, full g-unroll
// to maximize loads-in-flight (MLP).
__global__ void __launch_bounds__(256)
sample_kernel(const float* __restrict__ xyz,
              const float* __restrict__ boundp,
              float* __restrict__ out, int npts)
{
    int warp_g = (int)((blockIdx.x * (unsigned)blockDim.x + threadIdx.x) >> 5);
    int lane = threadIdx.x & 31;
    int sub  = lane >> 3;
    int sl2  = lane & 7;
    int gw   = warp_g * 4 + sub;
    if (gw >= npts) return;

    float invb = 1.0f / boundp[0];
    float p[3];
    p[0] = xyz[3*gw + 0] * invb;
    p[1] = xyz[3*gw + 1] * invb;
    p[2] = xyz[3*gw + 2] * invb;

    float wa0[3], wa1[3];
    int   c0i[3], c1i[3];
#pragma unroll
    for (int a = 0; a < 3; a++){
        float ia = (p[a] + 1.0f) * 0.5f * 159.0f;
        float fl = floorf(ia);
        float w  = ia - fl;
        int i0 = (int)fl, i1 = i0 + 1;
        float v0 = (i0 >= 0 && i0 <= 159) ? 1.0f : 0.0f;
        float v1 = (i1 >= 0 && i1 <= 159) ? 1.0f : 0.0f;
        c0i[a] = max(0, min(159, i0));
        c1i[a] = max(0, min(159, i1));
        wa0[a] = (1.0f - w) * v0;
        wa1[a] = w * v1;
    }

    const __half2* fld = &g_field_h[0][0][0][0];
    bool hi = (sl2 & 1) != 0;
    float acc0 = 0.0f, acc1 = 0.0f, acc2 = 0.0f, acc3 = 0.0f;

#pragma unroll
    for (int t = 0; t < 3; t++){
        const int ax = (t == 2) ? 0 : 2;
        const int ay = (t == 1) ? 0 : 1;

        __half2 w00h = __float2half2_rn(wa0[ax] * wa0[ay]);
        __half2 w01h = __float2half2_rn(wa1[ax] * wa0[ay]);
        __half2 w10h = __float2half2_rn(wa0[ax] * wa1[ay]);
        __half2 w11h = __float2half2_rn(wa1[ax] * wa1[ay]);

        int i0 = c0i[ax], i1 = c1i[ax];
        int j0 = c0i[ay], j1 = c1i[ay];

        const __half2* bp = fld + t * GS * GS * KD;
        const uint4* q00 = (const uint4*)(bp + (j0 * GS + i0) * KD) + sl2;
        const uint4* q01 = (const uint4*)(bp + (j0 * GS + i1) * KD) + sl2;
        const uint4* q10 = (const uint4*)(bp + (j1 * GS + i0) * KD) + sl2;
        const uint4* q11 = (const uint4*)(bp + (j1 * GS + i1) * KD) + sl2;

        float xt = (p[t] + 1.0f) * 0.5f;
        float s1, c1;
        sincospif(2.0f * xt, &s1, &c1);
        float cd[8], sd[8];
        cd[0] = 1.0f; sd[0] = 0.0f;
        float cc = c1, ss = s1;
        cd[1] = 2.0f * cc; sd[1] = 2.0f * ss;
#pragma unroll
        for (int j = 2; j < 8; j++){
            float nc = cc * cc - ss * ss;
            float ns = 2.0f * cc * ss;
            cc = nc; ss = ns;
            cd[j] = 2.0f * cc; sd[j] = 2.0f * ss;
        }
        float cs0 = hi ? cd[4] : cd[0], ss0 = hi ? sd[4] : sd[0];
        float cs1 = hi ? cd[5] : cd[1], ss1 = hi ? sd[5] : sd[1];
        float cs2 = hi ? cd[6] : cd[2], ss2 = hi ? sd[6] : sd[2];
        float cs3 = hi ? cd[7] : cd[3], ss3 = hi ? sd[7] : sd[3];

#pragma unroll
        for (int g = 0; g < 4; g++){
            uint4 u00 = q00[g * 8], u01 = q01[g * 8];
            uint4 u10 = q10[g * 8], u11 = q11[g * 8];
            float acc_s = 0.0f;
#pragma unroll
            for (int c = 0; c < 4; c++){
                __half2 acc = __hmul2(*(__half2*)&((&u00.x)[c]), w00h);
                acc = __hfma2(*(__half2*)&((&u01.x)[c]), w01h, acc);
                acc = __hfma2(*(__half2*)&((&u10.x)[c]), w10h, acc);
                acc = __hfma2(*(__half2*)&((&u11.x)[c]), w11h, acc);
                float2 f = __half22float2(acc);
                float csv = (c == 0) ? cs0 : (c == 1) ? cs1 : (c == 2) ? cs2 : cs3;
                float ssv = (c == 0) ? ss0 : (c == 1) ? ss1 : (c == 2) ? ss2 : ss3;
                acc_s += f.x * csv - f.y * ssv;
            }
            if      (g == 0) acc0 += acc_s;
            else if (g == 1) acc1 += acc_s;
            else if (g == 2) acc2 += acc_s;
            else             acc3 += acc_s;
        }
    }

    acc0 += __shfl_xor_sync(0xffffffffu, acc0, 1);
    acc1 += __shfl_xor_sync(0xffffffffu, acc1, 1);
    acc2 += __shfl_xor_sync(0xffffffffu, acc2, 1);
    acc3 += __shfl_xor_sync(0xffffffffu, acc3, 1);

    int q = sl2 >> 1;
    float* po = out + gw * NKS;
    if (!hi){
        po[q]      = acc0 * INV_FSCALE;
        po[4 + q]  = acc1 * INV_FSCALE;
    } else {
        po[8 + q]  = acc2 * INV_FSCALE;
        po[12 + q] = acc3 * INV_FSCALE;
    }
}

extern "C" void kernel_launch(void* const* d_in, const int* in_sizes, int n_in,
                              void* d_out, int out_size)
{
    const float* xyz   = (const float*)d_in[0];
    const float* bound = (const float*)d_in[1];
    const float* alpha = (const float*)d_in[2];
    const float* pur   = (const float*)d_in[3];
    const float* pui   = (const float*)d_in[4];
    const float* pvr   = (const float*)d_in[5];
    const float* pvi   = (const float*)d_in[6];
    const float* pwr   = (const float*)d_in[7];
    const float* pwi   = (const float*)d_in[8];

    pass1_kernel<<<SPEC_GRID, 256>>>(pur, pui, pvr, pvi, pwr, pwi, alpha);
    pass2_kernel<<<SPEC_GRID, 256>>>();

    int npts = in_sizes[0] / 3;
    int nwarps = (npts + 3) / 4;
    int nblocks = (nwarps * 32 + 255) / 256;
    sample_kernel<<<nblocks, 256>>>(xyz, bound, (float*)d_out, npts);
}